// round 13
// baseline (speedup 1.0000x reference)
#include <cuda_runtime.h>
#include <math.h>

// IDWT 1D (db4), banded synthesis:
//   even j=2i  : L[i+1]*bl1 + L[i]*bl3 + L[i-1]*bl5 + L[i-2]*bl7  (+ H w/ bh)
//   odd  j=2i+1: L[i+2]*bl0 + L[i+1]*bl2 + L[i]*bl4 + L[i-1]*bl6  (+ H w/ bh)
//
// Taps are the fixed db4 synthesis filters as compile-time immediates
// (FFMA-imm fast path, no tap loads).
//
// Each thread: 1 float4 load of L, 1 of H, halo via warp shuffle,
// 8 outputs = 2 float4 streaming stores.
//
// launch_bounds(256, 6): allows ~40 regs (no local-memory spills) while
// keeping 48 warps/SM — the (256,7)=32-reg variant spilled and issued ~2x
// the instructions.

#define BL0  0.23037781330885523f
#define BL1  0.7148465705525415f
#define BL2  0.6308807679295904f
#define BL3 -0.02798376941698385f
#define BL4 -0.18703481171888114f
#define BL5  0.030841381835986965f
#define BL6  0.032883011666982945f
#define BL7 -0.010597401784997278f

#define BH0 -0.010597401784997278f
#define BH1  0.032883011666982945f
#define BH2  0.030841381835986965f
#define BH3  0.18703481171888114f
#define BH4 -0.02798376941698385f
#define BH5 -0.6308807679295904f
#define BH6  0.7148465705525415f
#define BH7 -0.23037781330885523f

__global__ void __launch_bounds__(256, 6)
idwt1d_db4_kernel(const float* __restrict__ L,
                  const float* __restrict__ H,
                  float* __restrict__ out,
                  int Lh)
{
    const int W    = 2 * Lh;
    const int row  = blockIdx.y;
    const int nt   = Lh >> 2;                 // threads per row
    const int t    = blockIdx.x * blockDim.x + threadIdx.x;
    if (t >= nt) return;

    const int lane = threadIdx.x & 31;
    const int c0   = 4 * t;                   // thread owns L/H[c0 .. c0+3]

    const float* __restrict__ Lr = L + (size_t)row * Lh;
    const float* __restrict__ Hr = H + (size_t)row * Lh;

    const float4 l = *reinterpret_cast<const float4*>(Lr + c0);
    const float4 h = *reinterpret_cast<const float4*>(Hr + c0);

    // Halo from neighboring lanes (adjacent lanes = adjacent coarse quads).
    float lm2 = __shfl_up_sync(0xffffffffu, l.z, 1);
    float lm1 = __shfl_up_sync(0xffffffffu, l.w, 1);
    float hm2 = __shfl_up_sync(0xffffffffu, h.z, 1);
    float hm1 = __shfl_up_sync(0xffffffffu, h.w, 1);
    float lp4 = __shfl_down_sync(0xffffffffu, l.x, 1);
    float lp5 = __shfl_down_sync(0xffffffffu, l.y, 1);
    float hp4 = __shfl_down_sync(0xffffffffu, h.x, 1);
    float hp5 = __shfl_down_sync(0xffffffffu, h.y, 1);

    // Warp-edge fixups; hoisted predicates -> predicated loads, no BSSY.
    const bool e0a = (lane == 0) && (c0 >= 2);
    const bool e0b = (lane == 0) && (c0 >= 1);
    const bool e1a = (lane == 31) && (c0 + 4 < Lh);
    const bool e1b = (lane == 31) && (c0 + 5 < Lh);
    if (lane == 0)  { lm2 = 0.0f; lm1 = 0.0f; hm2 = 0.0f; hm1 = 0.0f; }
    if (lane == 31) { lp4 = 0.0f; lp5 = 0.0f; hp4 = 0.0f; hp5 = 0.0f; }
    if (e0a) { lm2 = __ldg(Lr + c0 - 2); hm2 = __ldg(Hr + c0 - 2); }
    if (e0b) { lm1 = __ldg(Lr + c0 - 1); hm1 = __ldg(Hr + c0 - 1); }
    if (e1a) { lp4 = __ldg(Lr + c0 + 4); hp4 = __ldg(Hr + c0 + 4); }
    if (e1b) { lp5 = __ldg(Lr + c0 + 5); hp5 = __ldg(Hr + c0 + 5); }

    // la[k] = L[c0-2+k], k=0..7
    const float la[8] = { lm2, lm1, l.x, l.y, l.z, l.w, lp4, lp5 };
    const float ha[8] = { hm2, hm1, h.x, h.y, h.z, h.w, hp4, hp5 };

    float o[8];
#pragma unroll
    for (int m = 0; m < 4; m++) {
        // even j = 2*(c0+m): taps la[m..m+3]
        o[2 * m] =
            fmaf(la[m + 3], BL1, fmaf(la[m + 2], BL3, fmaf(la[m + 1], BL5, la[m] * BL7))) +
            fmaf(ha[m + 3], BH1, fmaf(ha[m + 2], BH3, fmaf(ha[m + 1], BH5, ha[m] * BH7)));
        // odd j = 2*(c0+m)+1: taps la[m+1..m+4]
        o[2 * m + 1] =
            fmaf(la[m + 4], BL0, fmaf(la[m + 3], BL2, fmaf(la[m + 2], BL4, la[m + 1] * BL6))) +
            fmaf(ha[m + 4], BH0, fmaf(ha[m + 3], BH2, fmaf(ha[m + 2], BH4, ha[m + 1] * BH6)));
    }

    float4* op = reinterpret_cast<float4*>(out + (size_t)row * W + 8 * (size_t)t);
    __stcs(op,     make_float4(o[0], o[1], o[2], o[3]));
    __stcs(op + 1, make_float4(o[4], o[5], o[6], o[7]));
}

extern "C" void kernel_launch(void* const* d_in, const int* in_sizes, int n_in,
                              void* d_out, int out_size)
{
    const float* L = (const float*)d_in[0];
    const float* H = (const float*)d_in[1];
    float* out = (float*)d_out;

    long long msz = (long long)in_sizes[2];
    int Lh   = (int)(sqrt((double)(msz / 2)) + 0.5);
    int rows = in_sizes[0] / Lh;              // N*C
    int nt   = Lh >> 2;                       // threads per row

    dim3 block(256);
    dim3 grid((nt + block.x - 1) / block.x, rows);
    idwt1d_db4_kernel<<<grid, block>>>(L, H, out, Lh);
}